// round 3
// baseline (speedup 1.0000x reference)
#include <cuda_runtime.h>
#include <math.h>

#define B_   32
#define S_   2048
#define D_   400
#define H_   512

// __device__ scratch (allocation-free requirement)
__device__ float g_q   [(long)B_*S_*H_];   // [b][s][h]   (tf32-rounded)
__device__ float g_k   [(long)B_*S_*H_];   // [b][s][h]   (tf32-rounded)
__device__ float g_vT  [(long)B_*H_*S_];   // [b][h][s]   (tf32-rounded)
__device__ float g_att [(long)B_*S_*S_];   // [b][q][k]   (tf32-rounded post-softmax)
__device__ float g_out [(long)B_*S_*H_];   // [b][q][h]   (tf32-rounded)
__device__ float g_proj[(long)B_*S_*D_];   // [b][q][d]   (full fp32)
__device__ float g_rgbR [(long)B_*S_*D_];  // tf32-rounded rgb
__device__ float g_poseR[(long)B_*S_*D_];  // tf32-rounded pose
__device__ float g_WqT [H_*D_];
__device__ float g_WkT [H_*D_];
__device__ float g_WvT [H_*D_];
__device__ float g_WpT [D_*H_];

// ---------------------------------------------------------------------------
__device__ __forceinline__ unsigned f2tf32(float x) {
    unsigned u;
    asm("cvt.rna.tf32.f32 %0, %1;" : "=r"(u) : "f"(x));
    return u;
}
__device__ __forceinline__ float roundtf(float x) {
    return __uint_as_float(f2tf32(x));
}

// transpose + round: out[c*R + r] = tf32(in[r*C + c])
__global__ void transpose_round_k(const float* __restrict__ in, float* __restrict__ out,
                                  int R, int C) {
    int idx = blockIdx.x * blockDim.x + threadIdx.x;
    if (idx < R * C) {
        int r = idx / C, c = idx % C;
        out[c * R + r] = roundtf(in[idx]);
    }
}

// elementwise tf32 rounding copy (n multiple of 4)
__global__ void round_copy_k(const float* __restrict__ in, float* __restrict__ out, int n4) {
    int idx = blockIdx.x * blockDim.x + threadIdx.x;
    if (idx < n4) {
        float4 v = ((const float4*)in)[idx];
        v.x = roundtf(v.x); v.y = roundtf(v.y);
        v.z = roundtf(v.z); v.w = roundtf(v.w);
        ((float4*)out)[idx] = v;
    }
}

#define SMEM_LD 20   // 16 k-floats + 4 pad => (20*g + tg) mod 32 conflict-free

// ---------------------------------------------------------------------------
// NT GEMM on tensor cores (tf32 mma.sync m16n8k8), operands pre-rounded.
// C[m][n] = alpha * sum_k A[m][k]*B[n][k] (+bias_n[n]) (+bias_m[m]) [tf32-round]
// Block 128x128x16, 128 thr = 4 warps (2x2 of 64x64 warp tiles),
// cp.async double buffer. Requires M%128==0, K%16==0; N tail guarded.
// ---------------------------------------------------------------------------
__global__ void __launch_bounds__(128, 2)
gemm_tf32(const float* __restrict__ A, long sA,
          const float* __restrict__ B, long sB,
          float* __restrict__ C, long sC,
          int M, int N, int K, float alpha,
          const float* __restrict__ bias_n,
          const float* __restrict__ bias_m,
          int round_c) {
    __shared__ float As[2][128 * SMEM_LD];
    __shared__ float Bs[2][128 * SMEM_LD];

    const int tid  = threadIdx.x;
    const int lane = tid & 31;
    const int wid  = tid >> 5;       // 0..3
    const int wr   = wid & 1;        // warp row -> 64 rows
    const int wc   = wid >> 1;       // warp col -> 64 cols
    const int g    = lane >> 2;      // groupID 0..7
    const int tg   = lane & 3;       // thread-in-group 0..3

    const long bz = blockIdx.z;
    A += bz * sA; B += bz * sB; C += bz * sC;
    const int m0 = blockIdx.y * 128;
    const int n0 = blockIdx.x * 128;

    // copy mapping: 128 thr, each does 4 rows (ldr + 32r), one float4 of k
    const int ldr = tid >> 2;            // 0..31
    const int ldc = (tid & 3) * 4;       // 0,4,8,12

    const float* Ag = A + (long)(m0 + ldr) * K + ldc;
    const float* Bg[4];
    unsigned zB[4];
#pragma unroll
    for (int r = 0; r < 4; r++) {
        int bn = n0 + ldr + 32 * r;
        bool v = bn < N;
        Bg[r] = B + (long)(v ? bn : 0) * K + ldc;
        zB[r] = v ? 16u : 0u;
    }

    unsigned sa[2], sb[2];
    sa[0] = (unsigned)__cvta_generic_to_shared(&As[0][ldr * SMEM_LD + ldc]);
    sa[1] = (unsigned)__cvta_generic_to_shared(&As[1][ldr * SMEM_LD + ldc]);
    sb[0] = (unsigned)__cvta_generic_to_shared(&Bs[0][ldr * SMEM_LD + ldc]);
    sb[1] = (unsigned)__cvta_generic_to_shared(&Bs[1][ldr * SMEM_LD + ldc]);
    const unsigned rstep = 32 * SMEM_LD * 4;   // 32 rows in bytes

    float acc[4][8][4];
#pragma unroll
    for (int i = 0; i < 4; i++)
#pragma unroll
        for (int j = 0; j < 8; j++)
#pragma unroll
            for (int c = 0; c < 4; c++) acc[i][j][c] = 0.f;

    const int T = K / 16;
    const long Astep = (long)32 * K;

    // prologue: stage 0
#pragma unroll
    for (int r = 0; r < 4; r++) {
        asm volatile("cp.async.cg.shared.global [%0], [%1], 16;\n"
                     :: "r"(sa[0] + r * rstep), "l"(Ag + r * Astep));
        asm volatile("cp.async.cg.shared.global [%0], [%1], 16, %2;\n"
                     :: "r"(sb[0] + r * rstep), "l"(Bg[r]), "r"(zB[r]));
    }
    asm volatile("cp.async.commit_group;\n");

    for (int t = 0; t < T; t++) {
        const int buf = t & 1;
        if (t + 1 < T) {
            const int nb = buf ^ 1;
            const long k0 = (long)(t + 1) * 16;
#pragma unroll
            for (int r = 0; r < 4; r++) {
                asm volatile("cp.async.cg.shared.global [%0], [%1], 16;\n"
                             :: "r"(sa[nb] + r * rstep), "l"(Ag + r * Astep + k0));
                asm volatile("cp.async.cg.shared.global [%0], [%1], 16, %2;\n"
                             :: "r"(sb[nb] + r * rstep), "l"(Bg[r] + k0), "r"(zB[r]));
            }
            asm volatile("cp.async.commit_group;\n");
            asm volatile("cp.async.wait_group 1;\n");
        } else {
            asm volatile("cp.async.wait_group 0;\n");
        }
        __syncthreads();

#pragma unroll
        for (int kk = 0; kk < 16; kk += 8) {
            unsigned af[4][4], bf[8][2];
#pragma unroll
            for (int i = 0; i < 4; i++) {
                const float* p = &As[buf][(wr * 64 + i * 16 + g) * SMEM_LD + kk + tg];
                af[i][0] = __float_as_uint(p[0]);
                af[i][1] = __float_as_uint(p[8 * SMEM_LD]);
                af[i][2] = __float_as_uint(p[4]);
                af[i][3] = __float_as_uint(p[8 * SMEM_LD + 4]);
            }
#pragma unroll
            for (int j = 0; j < 8; j++) {
                const float* p = &Bs[buf][(wc * 64 + j * 8 + g) * SMEM_LD + kk + tg];
                bf[j][0] = __float_as_uint(p[0]);
                bf[j][1] = __float_as_uint(p[4]);
            }
#pragma unroll
            for (int i = 0; i < 4; i++)
#pragma unroll
                for (int j = 0; j < 8; j++) {
                    asm volatile(
                        "mma.sync.aligned.m16n8k8.row.col.f32.tf32.tf32.f32 "
                        "{%0,%1,%2,%3}, {%4,%5,%6,%7}, {%8,%9}, {%0,%1,%2,%3};\n"
                        : "+f"(acc[i][j][0]), "+f"(acc[i][j][1]),
                          "+f"(acc[i][j][2]), "+f"(acc[i][j][3])
                        : "r"(af[i][0]), "r"(af[i][1]), "r"(af[i][2]), "r"(af[i][3]),
                          "r"(bf[j][0]), "r"(bf[j][1]));
                }
        }
        __syncthreads();
    }

    // epilogue
#pragma unroll
    for (int i = 0; i < 4; i++) {
        const int r0 = m0 + wr * 64 + i * 16 + g;
        const int r1 = r0 + 8;
        const float bm0 = bias_m ? bias_m[r0] : 0.f;
        const float bm1 = bias_m ? bias_m[r1] : 0.f;
#pragma unroll
        for (int j = 0; j < 8; j++) {
            const int c0 = n0 + wc * 64 + j * 8 + 2 * tg;
            if (c0 < N) {
                const float bnl = bias_n ? bias_n[c0]     : 0.f;
                const float bnh = bias_n ? bias_n[c0 + 1] : 0.f;
                float v00 = acc[i][j][0] * alpha + bm0 + bnl;
                float v01 = acc[i][j][1] * alpha + bm0 + bnh;
                float v10 = acc[i][j][2] * alpha + bm1 + bnl;
                float v11 = acc[i][j][3] * alpha + bm1 + bnh;
                if (round_c) {
                    v00 = roundtf(v00); v01 = roundtf(v01);
                    v10 = roundtf(v10); v11 = roundtf(v11);
                }
                *(float2*)&C[(long)r0 * N + c0] = make_float2(v00, v01);
                *(float2*)&C[(long)r1 * N + c0] = make_float2(v10, v11);
            }
        }
    }
}

// ---------------------------------------------------------------------------
// Row softmax over 2048 cols; rounds result to tf32 for the AV GEMM.
// ---------------------------------------------------------------------------
__global__ void __launch_bounds__(256)
softmax2048(float* __restrict__ data) {
    float* row = data + (long)blockIdx.x * 2048;
    const int tid = threadIdx.x;
    __shared__ float red[8];

    float v[8];
    float m = -3.4e38f;
#pragma unroll
    for (int i = 0; i < 8; i++) { v[i] = row[tid + i * 256]; m = fmaxf(m, v[i]); }
#pragma unroll
    for (int o = 16; o > 0; o >>= 1) m = fmaxf(m, __shfl_xor_sync(~0u, m, o));
    if ((tid & 31) == 0) red[tid >> 5] = m;
    __syncthreads();
    float rowmax = red[0];
#pragma unroll
    for (int w = 1; w < 8; w++) rowmax = fmaxf(rowmax, red[w]);
    __syncthreads();

    float s = 0.f;
#pragma unroll
    for (int i = 0; i < 8; i++) { v[i] = __expf(v[i] - rowmax); s += v[i]; }
#pragma unroll
    for (int o = 16; o > 0; o >>= 1) s += __shfl_xor_sync(~0u, s, o);
    if ((tid & 31) == 0) red[tid >> 5] = s;
    __syncthreads();
    float tot = 0.f;
#pragma unroll
    for (int w = 0; w < 8; w++) tot += red[w];
    float inv = 1.f / tot;
#pragma unroll
    for (int i = 0; i < 8; i++) row[tid + i * 256] = roundtf(v[i] * inv);
}

// ---------------------------------------------------------------------------
__global__ void __launch_bounds__(128)
ln_epilogue(const float* __restrict__ proj, const float* __restrict__ rgb,
            const float* __restrict__ gate, const float* __restrict__ gamma,
            const float* __restrict__ beta, float* __restrict__ out) {
    const long row = blockIdx.x;
    const int tid = threadIdx.x;
    const float g = gate[0];
    __shared__ float xs[D_];
    __shared__ float red[4];

    float s = 0.f;
    for (int i = tid; i < D_; i += 128) {
        float x = rgb[row * D_ + i] + g * proj[row * D_ + i];
        xs[i] = x;
        s += x;
    }
#pragma unroll
    for (int o = 16; o > 0; o >>= 1) s += __shfl_xor_sync(~0u, s, o);
    if ((tid & 31) == 0) red[tid >> 5] = s;
    __syncthreads();
    float mu = (red[0] + red[1] + red[2] + red[3]) * (1.0f / D_);
    __syncthreads();

    float vs = 0.f;
    for (int i = tid; i < D_; i += 128) {
        float d = xs[i] - mu;
        vs += d * d;
    }
#pragma unroll
    for (int o = 16; o > 0; o >>= 1) vs += __shfl_xor_sync(~0u, vs, o);
    if ((tid & 31) == 0) red[tid >> 5] = vs;
    __syncthreads();
    float var = (red[0] + red[1] + red[2] + red[3]) * (1.0f / D_);
    float inv = rsqrtf(var + 1e-5f);

    for (int i = tid; i < D_; i += 128) {
        out[row * D_ + i] = (xs[i] - mu) * inv * gamma[i] + beta[i];
    }
}

// ---------------------------------------------------------------------------
static float* sym(const void* s) {
    void* p = nullptr;
    cudaGetSymbolAddress(&p, s);
    return (float*)p;
}

extern "C" void kernel_launch(void* const* d_in, const int* in_sizes, int n_in,
                              void* d_out, int out_size) {
    const float* rgb   = (const float*)d_in[0];
    const float* pose  = (const float*)d_in[1];
    const float* Wq    = (const float*)d_in[2];
    const float* bq    = (const float*)d_in[3];
    const float* Wk    = (const float*)d_in[4];
    const float* bk    = (const float*)d_in[5];
    const float* Wv    = (const float*)d_in[6];
    const float* bv    = (const float*)d_in[7];
    const float* Wp    = (const float*)d_in[8];
    const float* bp    = (const float*)d_in[9];
    const float* gamma = (const float*)d_in[10];
    const float* beta  = (const float*)d_in[11];
    const float* gate  = (const float*)d_in[12];
    float* out = (float*)d_out;

    float* q     = sym(g_q);
    float* k     = sym(g_k);
    float* vT    = sym(g_vT);
    float* att   = sym(g_att);
    float* o     = sym(g_out);
    float* proj  = sym(g_proj);
    float* rgbR  = sym(g_rgbR);
    float* poseR = sym(g_poseR);
    float* WqT   = sym(g_WqT);
    float* WkT   = sym(g_WkT);
    float* WvT   = sym(g_WvT);
    float* WpT   = sym(g_WpT);

    const int MS = B_ * S_;               // 65536
    const float inv_sqrt_h = 0.044194173824159216f;  // 1/sqrt(512)

    // rounded weight transposes + rounded activation copies
    {
        int n1 = D_ * H_;
        transpose_round_k<<<(n1 + 255) / 256, 256>>>(Wq, WqT, D_, H_);
        transpose_round_k<<<(n1 + 255) / 256, 256>>>(Wk, WkT, D_, H_);
        transpose_round_k<<<(n1 + 255) / 256, 256>>>(Wv, WvT, D_, H_);
        transpose_round_k<<<(n1 + 255) / 256, 256>>>(Wp, WpT, H_, D_);
        int n4 = MS * D_ / 4;
        round_copy_k<<<(n4 + 255) / 256, 256>>>(rgb, rgbR, n4);
        round_copy_k<<<(n4 + 255) / 256, 256>>>(pose, poseR, n4);
    }

    // q = rgb @ Wq + bq  (rounded output)
    gemm_tf32<<<dim3(H_ / 128, MS / 128, 1), 128>>>(
        rgbR, 0, WqT, 0, q, 0, MS, H_, D_, 1.f, bq, nullptr, 1);
    // k = pose @ Wk + bk (rounded output)
    gemm_tf32<<<dim3(H_ / 128, MS / 128, 1), 128>>>(
        poseR, 0, WkT, 0, k, 0, MS, H_, D_, 1.f, bk, nullptr, 1);
    // vT[b][h][s] = (pose_b @ Wv + bv)^T (rounded output)
    gemm_tf32<<<dim3(S_ / 128, H_ / 128, B_), 128>>>(
        WvT, 0, poseR, (long)S_ * D_, vT, (long)H_ * S_,
        H_, S_, D_, 1.f, nullptr, bv, 1);

    // scores[b][q][k] = q_b . k_b / sqrt(H)  (full precision into softmax)
    gemm_tf32<<<dim3(S_ / 128, S_ / 128, B_), 128>>>(
        q, (long)S_ * H_, k, (long)S_ * H_, att, (long)S_ * S_,
        S_, S_, H_, inv_sqrt_h, nullptr, nullptr, 0);

    // softmax rows (rounds output to tf32)
    softmax2048<<<B_ * S_, 256>>>(att);

    // out[b][q][h] = attn_b @ v_b  (rounded output)
    gemm_tf32<<<dim3(H_ / 128, S_ / 128, B_), 128>>>(
        att, (long)S_ * S_, vT, (long)H_ * S_, o, (long)S_ * H_,
        S_, H_, S_, 1.f, nullptr, nullptr, 1);

    // proj = out @ Wp + bp  (full precision, N=400 tail guarded)
    gemm_tf32<<<dim3((D_ + 127) / 128, MS / 128, 1), 128>>>(
        o, 0, WpT, 0, proj, 0, MS, D_, H_, 1.f, bp, nullptr, 0);

    // fused = LN(rgb + gate*proj)
    ln_epilogue<<<B_ * S_, 128>>>(proj, rgb, gate, gamma, beta, out);
}